// round 7
// baseline (speedup 1.0000x reference)
#include <cuda_runtime.h>

// Problem constants
namespace {
constexpr int B  = 4;
constexpr int S  = 1024;
constexpr int DM = 512;
constexpr int DA = 512;
constexpr int H  = 8;
constexpr int F  = 16;
}

// Scratch (static device globals -- no allocations allowed)
__device__ float g_qp [B * S * DA];      // 8 MB
__device__ float g_kp [B * S * DA];      // 8 MB
__device__ float g_vp [B * S * DA];      // 8 MB
__device__ float g_x  [B * S * H * F];   // 2 MB
__device__ float g_ctx[B * S * DA];      // 8 MB

// ---------------------------------------------------------------------------
// tf32 helpers
// ---------------------------------------------------------------------------
__device__ __forceinline__ unsigned f2tf(float f) {
    unsigned u;
    asm("cvt.rna.tf32.f32 %0, %1;" : "=r"(u) : "f"(f));
    return u;
}

__device__ __forceinline__ void mma_tf32(float c[4],
                                         unsigned a0, unsigned a1, unsigned a2, unsigned a3,
                                         unsigned b0, unsigned b1) {
    asm volatile(
        "mma.sync.aligned.m16n8k8.row.col.f32.tf32.tf32.f32 "
        "{%0,%1,%2,%3}, {%4,%5,%6,%7}, {%8,%9}, {%0,%1,%2,%3};"
        : "+f"(c[0]), "+f"(c[1]), "+f"(c[2]), "+f"(c[3])
        : "r"(a0), "r"(a1), "r"(a2), "r"(a3), "r"(b0), "r"(b1));
}

// ---------------------------------------------------------------------------
// 64x64-tile tf32 GEMM body: C[m0:64, n0:64] = A[M,K] @ W[K,N] + bias
// 128 threads (4 warps, warp-tile 32x32), BK=16, reg-prefetch double buffer.
// K % 16 == 0.
// ---------------------------------------------------------------------------
__device__ __forceinline__ void gemm64_body(
    const float* __restrict__ A, const float* __restrict__ W,
    const float* __restrict__ bias, float* __restrict__ C,
    int N, int K, int m0, int n0)
{
    constexpr int AS = 20;   // As[m][k], 16+4
    constexpr int BS = 72;   // Bs[k][n], 64+8
    __shared__ unsigned As[64 * AS];
    __shared__ unsigned Bs[16 * BS];

    const int tid  = threadIdx.x;
    const int warp = tid >> 5;
    const int lane = tid & 31;
    const int gid  = lane >> 2;
    const int tig  = lane & 3;
    const int wm   = (warp & 1) * 32;
    const int wn   = (warp >> 1) * 32;

    float4 ra[2], rb[2];
#pragma unroll
    for (int p = 0; p < 2; p++) {
        const int ia = tid + p * 128;
        ra[p] = *(const float4*)&A[(size_t)(m0 + (ia >> 2)) * K + (ia & 3) * 4];
        const int ib = tid + p * 128;
        rb[p] = *(const float4*)&W[(size_t)(ib >> 4) * N + n0 + (ib & 15) * 4];
    }

    float acc[2][4][4] = {};

    for (int k0 = 0; k0 < K; k0 += 16) {
#pragma unroll
        for (int p = 0; p < 2; p++) {
            const int ia = tid + p * 128;
            unsigned* pa = &As[(ia >> 2) * AS + (ia & 3) * 4];
            pa[0] = f2tf(ra[p].x); pa[1] = f2tf(ra[p].y);
            pa[2] = f2tf(ra[p].z); pa[3] = f2tf(ra[p].w);
            const int ib = tid + p * 128;
            unsigned* pb = &Bs[(ib >> 4) * BS + (ib & 15) * 4];
            pb[0] = f2tf(rb[p].x); pb[1] = f2tf(rb[p].y);
            pb[2] = f2tf(rb[p].z); pb[3] = f2tf(rb[p].w);
        }
        __syncthreads();
        if (k0 + 16 < K) {
#pragma unroll
            for (int p = 0; p < 2; p++) {
                const int ia = tid + p * 128;
                ra[p] = *(const float4*)&A[(size_t)(m0 + (ia >> 2)) * K + k0 + 16 + (ia & 3) * 4];
                const int ib = tid + p * 128;
                rb[p] = *(const float4*)&W[(size_t)(k0 + 16 + (ib >> 4)) * N + n0 + (ib & 15) * 4];
            }
        }
#pragma unroll
        for (int ks = 0; ks < 2; ks++) {
            unsigned afr[2][4];
#pragma unroll
            for (int mi = 0; mi < 2; mi++) {
                const int mr = wm + mi * 16 + gid;
                afr[mi][0] = As[mr * AS + ks * 8 + tig];
                afr[mi][1] = As[(mr + 8) * AS + ks * 8 + tig];
                afr[mi][2] = As[mr * AS + ks * 8 + tig + 4];
                afr[mi][3] = As[(mr + 8) * AS + ks * 8 + tig + 4];
            }
            unsigned bfr[4][2];
#pragma unroll
            for (int ni = 0; ni < 4; ni++) {
                const int nc = wn + ni * 8 + gid;
                bfr[ni][0] = Bs[(ks * 8 + tig) * BS + nc];
                bfr[ni][1] = Bs[(ks * 8 + tig + 4) * BS + nc];
            }
#pragma unroll
            for (int mi = 0; mi < 2; mi++)
#pragma unroll
                for (int ni = 0; ni < 4; ni++)
                    mma_tf32(acc[mi][ni], afr[mi][0], afr[mi][1], afr[mi][2], afr[mi][3],
                             bfr[ni][0], bfr[ni][1]);
        }
        __syncthreads();
    }

#pragma unroll
    for (int mi = 0; mi < 2; mi++) {
        const int row = m0 + wm + mi * 16 + gid;
#pragma unroll
        for (int ni = 0; ni < 4; ni++) {
            const int col = n0 + wn + ni * 8 + 2 * tig;
            const float2 bb = *(const float2*)&bias[col];
            float2 o0, o1;
            o0.x = acc[mi][ni][0] + bb.x; o0.y = acc[mi][ni][1] + bb.y;
            o1.x = acc[mi][ni][2] + bb.x; o1.y = acc[mi][ni][3] + bb.y;
            *(float2*)&C[(size_t)row * N + col]       = o0;
            *(float2*)&C[(size_t)(row + 8) * N + col] = o1;
        }
    }
}

// q/k/v projections batched over blockIdx.z
__global__ __launch_bounds__(128) void qkv_proj_kernel(
    const float* __restrict__ q, const float* __restrict__ k, const float* __restrict__ v,
    const float* __restrict__ Wq, const float* __restrict__ bq,
    const float* __restrict__ Wk, const float* __restrict__ bk,
    const float* __restrict__ Wv, const float* __restrict__ bv,
    float* __restrict__ qp, float* __restrict__ kp, float* __restrict__ vp)
{
    const int z = blockIdx.z;
    const float* A    = (z == 0) ? q  : (z == 1) ? k  : v;
    const float* W    = (z == 0) ? Wq : (z == 1) ? Wk : Wv;
    const float* bias = (z == 0) ? bq : (z == 1) ? bk : bv;
    float*       C    = (z == 0) ? qp : (z == 1) ? kp : vp;
    gemm64_body(A, W, bias, C, DA, DM, blockIdx.y * 64, blockIdx.x * 64);
}

// generic single GEMM (x projection, output projection)
__global__ __launch_bounds__(128) void gemm64_kernel(
    const float* __restrict__ A, const float* __restrict__ W,
    const float* __restrict__ bias, float* __restrict__ C, int N, int K)
{
    gemm64_body(A, W, bias, C, N, K, blockIdx.y * 64, blockIdx.x * 64);
}

// ---------------------------------------------------------------------------
// xdiff bias: logits[b,h,q,k] = 0.5 * sum_f xdiff[b,q,k,f] * x[b,q,h*F+f]
// One CTA per (b,q); reads xdiff exactly once, writes the logits buffer once.
// ---------------------------------------------------------------------------
__global__ __launch_bounds__(256) void xbias_kernel(
    const float* __restrict__ xdiff, const float* __restrict__ xg,
    float* __restrict__ logits)
{
    __shared__ float xh[H * F];
    const int bq  = blockIdx.x;
    const int b   = bq >> 10;
    const int qi  = bq & 1023;
    const int tid = threadIdx.x;
    if (tid < H * F) xh[tid] = xg[(size_t)bq * (H * F) + tid];
    __syncthreads();
    const float* xd = xdiff + (size_t)bq * S * F;
#pragma unroll
    for (int kt = 0; kt < 4; kt++) {
        const int k = kt * 256 + tid;
        const float4* src = (const float4*)&xd[(size_t)k * F];
        const float4 t0 = src[0], t1 = src[1], t2 = src[2], t3 = src[3];
        const float xv[16] = {t0.x, t0.y, t0.z, t0.w, t1.x, t1.y, t1.z, t1.w,
                              t2.x, t2.y, t2.z, t2.w, t3.x, t3.y, t3.z, t3.w};
#pragma unroll
        for (int h = 0; h < H; h++) {
            float s = 0.0f;
#pragma unroll
            for (int f = 0; f < F; f++) s = fmaf(xv[f], xh[h * F + f], s);
            logits[((size_t)(b * H + h) * S + qi) * S + k] = 0.5f * s;
        }
    }
}

// ---------------------------------------------------------------------------
// Fused attention: per CTA = (32-row q-tile, (b,h)).
//   L[32][1024] (smem) = bias tile (from gmem) + QK^T (tf32 mma, Q pre-scaled)
//   softmax(L) in smem -> write attn out
//   ctx tile = L @ V (tf32 mma) -> write ctx
// Grid ordered so consecutive CTAs share the same (b,h) K/V slices (L2 reuse).
// Dynamic smem: L 32x1044 + Qs 32x68 + KV 128x72  (179,200 B)
// ---------------------------------------------------------------------------
namespace {
constexpr int LSTR = 1044;
constexpr int QSTR = 68;
constexpr int KSTK = 68;   // K-phase stride (QK B-frags conflict-free)
constexpr int KSTV = 72;   // V-phase stride (PV B-frags conflict-free)
constexpr int FATTN_SMEM = (32 * LSTR + 32 * QSTR + 128 * KSTV) * 4;
}

__global__ __launch_bounds__(256) void fattn_kernel(
    const float* __restrict__ qp, const float* __restrict__ kp,
    const float* __restrict__ vp, float* __restrict__ attn,
    float* __restrict__ ctx)
{
    extern __shared__ float smem[];
    float*    L  = smem;                               // 32 x LSTR
    unsigned* Qs = (unsigned*)(smem + 32 * LSTR);      // 32 x QSTR
    unsigned* KV = Qs + 32 * QSTR;                     // 128 x KSTV

    const int tid  = threadIdx.x;
    const int warp = tid >> 5;
    const int lane = tid & 31;
    const int gid  = lane >> 2;
    const int tig  = lane & 3;

    const int bh = blockIdx.y;           // b*H + h
    const int b  = bh >> 3;
    const int h  = bh & 7;
    const int q0 = blockIdx.x * 32;

    const size_t bh_row0 = ((size_t)bh * S + q0) * S;

    // ---- load bias tile (written by xbias_kernel) into L ----
    for (int i = tid; i < 32 * 256; i += 256) {
        const int row = i >> 8;
        const int c4  = (i & 255) * 4;
        *(float4*)&L[row * LSTR + c4] = *(const float4*)&attn[bh_row0 + (size_t)row * S + c4];
    }

    // ---- load Q tile, pre-scaled by 1/sqrt(D)=0.125, tf32 ----
    for (int i = tid; i < 32 * 16; i += 256) {
        const int row = i >> 4;
        const int c4  = (i & 15) * 4;
        const float4 v = *(const float4*)&qp[(size_t)(b * S + q0 + row) * DA + h * 64 + c4];
        unsigned* p = &Qs[row * QSTR + c4];
        p[0] = f2tf(v.x * 0.125f); p[1] = f2tf(v.y * 0.125f);
        p[2] = f2tf(v.z * 0.125f); p[3] = f2tf(v.w * 0.125f);
    }
    __syncthreads();

    // ---- QK^T: accumulate into L (reduction over d=64: ks 0..7) ----
    const float* Kb = kp + (size_t)b * S * DA + h * 64;
    for (int kt = 0; kt < 8; kt++) {
        const int k0 = kt * 128;
        for (int i = tid; i < 128 * 16; i += 256) {
            const int row = i >> 4;
            const int c4  = (i & 15) * 4;
            const float4 v = *(const float4*)&Kb[(size_t)(k0 + row) * DA + c4];
            unsigned* p = &KV[row * KSTK + c4];
            p[0] = f2tf(v.x); p[1] = f2tf(v.y); p[2] = f2tf(v.z); p[3] = f2tf(v.w);
        }
        __syncthreads();

        float acc[2][2][4] = {};
#pragma unroll
        for (int ks = 0; ks < 8; ks++) {
            unsigned afr[2][4];
#pragma unroll
            for (int mi = 0; mi < 2; mi++) {
                const int mr = mi * 16 + gid;
                afr[mi][0] = Qs[mr * QSTR + ks * 8 + tig];
                afr[mi][1] = Qs[(mr + 8) * QSTR + ks * 8 + tig];
                afr[mi][2] = Qs[mr * QSTR + ks * 8 + tig + 4];
                afr[mi][3] = Qs[(mr + 8) * QSTR + ks * 8 + tig + 4];
            }
#pragma unroll
            for (int ni = 0; ni < 2; ni++) {
                const int nc = warp * 16 + ni * 8 + gid;
                const unsigned b0 = KV[nc * KSTK + ks * 8 + tig];
                const unsigned b1 = KV[nc * KSTK + ks * 8 + tig + 4];
#pragma unroll
                for (int mi = 0; mi < 2; mi++)
                    mma_tf32(acc[mi][ni], afr[mi][0], afr[mi][1], afr[mi][2], afr[mi][3],
                             b0, b1);
            }
        }
        // epilogue: L += acc (warp owns cols warp*16..+16 -> no races)
#pragma unroll
        for (int mi = 0; mi < 2; mi++) {
            const int row = mi * 16 + gid;
#pragma unroll
            for (int ni = 0; ni < 2; ni++) {
                const int col = k0 + warp * 16 + ni * 8 + tig * 2;
                L[row * LSTR + col]           += acc[mi][ni][0];
                L[row * LSTR + col + 1]       += acc[mi][ni][1];
                L[(row + 8) * LSTR + col]     += acc[mi][ni][2];
                L[(row + 8) * LSTR + col + 1] += acc[mi][ni][3];
            }
        }
        __syncthreads();
    }

    // ---- softmax (warp per 4 rows), write attn out + normalized back to L ----
#pragma unroll
    for (int r = 0; r < 4; r++) {
        const int row = warp * 4 + r;
        float* Lr = &L[row * LSTR];
        float4 v[8];
        float m = -1e30f;
#pragma unroll
        for (int c = 0; c < 8; c++) {
            v[c] = *(float4*)&Lr[c * 128 + lane * 4];
            m = fmaxf(m, fmaxf(fmaxf(v[c].x, v[c].y), fmaxf(v[c].z, v[c].w)));
        }
#pragma unroll
        for (int o = 16; o; o >>= 1) m = fmaxf(m, __shfl_xor_sync(0xffffffffu, m, o));
        float s = 0.0f;
#pragma unroll
        for (int c = 0; c < 8; c++) {
            v[c].x = __expf(v[c].x - m); v[c].y = __expf(v[c].y - m);
            v[c].z = __expf(v[c].z - m); v[c].w = __expf(v[c].w - m);
            s += v[c].x + v[c].y + v[c].z + v[c].w;
        }
#pragma unroll
        for (int o = 16; o; o >>= 1) s += __shfl_xor_sync(0xffffffffu, s, o);
        const float inv = 1.0f / s;
        float* Ar = attn + bh_row0 + (size_t)row * S;
#pragma unroll
        for (int c = 0; c < 8; c++) {
            v[c].x *= inv; v[c].y *= inv; v[c].z *= inv; v[c].w *= inv;
            *(float4*)&Lr[c * 128 + lane * 4] = v[c];
            *(float4*)&Ar[c * 128 + lane * 4] = v[c];
        }
    }
    __syncthreads();

    // ---- PV: ctx tile [32,64] = L @ V  (reduction over 128 keys/chunk: ks 0..15) ----
    const float* Vb = vp + (size_t)b * S * DA + h * 64;
    const int mi = warp & 1;
    const int wn = (warp >> 1) * 16;
    float pacc[2][4] = {};
    for (int kt = 0; kt < 8; kt++) {
        const int k0 = kt * 128;
        for (int i = tid; i < 128 * 16; i += 256) {
            const int row = i >> 4;
            const int c4  = (i & 15) * 4;
            const float4 v = *(const float4*)&Vb[(size_t)(k0 + row) * DA + c4];
            unsigned* p = &KV[row * KSTV + c4];
            p[0] = f2tf(v.x); p[1] = f2tf(v.y); p[2] = f2tf(v.z); p[3] = f2tf(v.w);
        }
        __syncthreads();
#pragma unroll
        for (int ks = 0; ks < 16; ks++) {        // FIX: 16 k8-steps = all 128 keys
            const int kk = k0 + ks * 8;
            const int row = mi * 16 + gid;
            const unsigned a0 = f2tf(L[row * LSTR + kk + tig]);
            const unsigned a1 = f2tf(L[(row + 8) * LSTR + kk + tig]);
            const unsigned a2 = f2tf(L[row * LSTR + kk + tig + 4]);
            const unsigned a3 = f2tf(L[(row + 8) * LSTR + kk + tig + 4]);
#pragma unroll
            for (int ni = 0; ni < 2; ni++) {
                const unsigned b0 = KV[(ks * 8 + tig) * KSTV + wn + ni * 8 + gid];
                const unsigned b1 = KV[(ks * 8 + tig + 4) * KSTV + wn + ni * 8 + gid];
                mma_tf32(pacc[ni], a0, a1, a2, a3, b0, b1);
            }
        }
        __syncthreads();
    }
    {
        const int grow = b * S + q0 + mi * 16 + gid;
#pragma unroll
        for (int ni = 0; ni < 2; ni++) {
            const int col = h * 64 + wn + ni * 8 + tig * 2;
            float2 o0, o1;
            o0.x = pacc[ni][0]; o0.y = pacc[ni][1];
            o1.x = pacc[ni][2]; o1.y = pacc[ni][3];
            *(float2*)&ctx[(size_t)grow * DA + col]       = o0;
            *(float2*)&ctx[(size_t)(grow + 8) * DA + col] = o1;
        }
    }
}

// ---------------------------------------------------------------------------
extern "C" void kernel_launch(void* const* d_in, const int* in_sizes, int n_in,
                              void* d_out, int out_size)
{
    const float* q     = (const float*)d_in[0];
    const float* k     = (const float*)d_in[1];
    const float* v     = (const float*)d_in[2];
    const float* xdiff = (const float*)d_in[3];
    const float* Wq    = (const float*)d_in[4];
    const float* bq    = (const float*)d_in[5];
    const float* Wk    = (const float*)d_in[6];
    const float* bk    = (const float*)d_in[7];
    const float* Wv    = (const float*)d_in[8];
    const float* bv    = (const float*)d_in[9];
    const float* Wx    = (const float*)d_in[10];
    const float* bx    = (const float*)d_in[11];
    const float* Wo    = (const float*)d_in[12];
    const float* bo    = (const float*)d_in[13];

    float* out_final = (float*)d_out;                       // [B,S,DM]
    float* attn      = out_final + (size_t)B * S * DM;      // [B,H,S,S]

    float *qp, *kp, *vp, *xg, *ctx;
    cudaGetSymbolAddress((void**)&qp,  g_qp);
    cudaGetSymbolAddress((void**)&kp,  g_kp);
    cudaGetSymbolAddress((void**)&vp,  g_vp);
    cudaGetSymbolAddress((void**)&xg,  g_x);
    cudaGetSymbolAddress((void**)&ctx, g_ctx);

    cudaFuncSetAttribute(fattn_kernel, cudaFuncAttributeMaxDynamicSharedMemorySize,
                         FATTN_SMEM);

    // 1. q/k/v projections, one batched launch: grid (N/64, M/64, 3)
    qkv_proj_kernel<<<dim3(DA / 64, (B * S) / 64, 3), 128>>>(
        q, k, v, Wq, bq, Wk, bk, Wv, bv, qp, kp, vp);

    // 2. x = qp @ Wx + bx : [4096,512] @ [512,128]
    gemm64_kernel<<<dim3((H * F) / 64, (B * S) / 64), 128>>>(qp, Wx, bx, xg, H * F, DA);

    // 3. xdiff relative bias -> writes entire logits buffer (attn region)
    xbias_kernel<<<B * S, 256>>>(xdiff, xg, attn);

    // 4. fused: logits += QK^T, softmax, attn out, PV -> ctx
    //    grid: x = q-tile (fast), y = (b,h)  => consecutive CTAs share K/V in L2
    fattn_kernel<<<dim3(S / 32, B * H), 256, FATTN_SMEM>>>(qp, kp, vp, attn, ctx);

    // 5. output = ctx @ Wo + bo
    gemm64_kernel<<<dim3(DM / 64, (B * S) / 64), 128>>>(ctx, Wo, bo, out_final, DM, DA);
}

// round 8
// speedup vs baseline: 1.5982x; 1.5982x over previous
#include <cuda_runtime.h>

// Problem constants
namespace {
constexpr int B  = 4;
constexpr int S  = 1024;
constexpr int DM = 512;
constexpr int DA = 512;
constexpr int H  = 8;
constexpr int F  = 16;
}

// Scratch (static device globals -- no allocations allowed)
__device__ float g_qp [B * S * DA];      // 8 MB
__device__ float g_kp [B * S * DA];      // 8 MB
__device__ float g_vp [B * S * DA];      // 8 MB
__device__ float g_x  [B * S * H * F];   // 2 MB
__device__ float g_ctx[B * S * DA];      // 8 MB

// ---------------------------------------------------------------------------
// tf32 helpers
// ---------------------------------------------------------------------------
__device__ __forceinline__ unsigned f2tf(float f) {
    unsigned u;
    asm("cvt.rna.tf32.f32 %0, %1;" : "=r"(u) : "f"(f));
    return u;
}

__device__ __forceinline__ void mma_tf32(float c[4],
                                         unsigned a0, unsigned a1, unsigned a2, unsigned a3,
                                         unsigned b0, unsigned b1) {
    asm volatile(
        "mma.sync.aligned.m16n8k8.row.col.f32.tf32.tf32.f32 "
        "{%0,%1,%2,%3}, {%4,%5,%6,%7}, {%8,%9}, {%0,%1,%2,%3};"
        : "+f"(c[0]), "+f"(c[1]), "+f"(c[2]), "+f"(c[3])
        : "r"(a0), "r"(a1), "r"(a2), "r"(a3), "r"(b0), "r"(b1));
}

// ---------------------------------------------------------------------------
// 64x64-tile tf32 GEMM body: C[m0:64, n0:64] = A[M,K] @ W[K,N] + bias
// 128 threads (4 warps, warp-tile 32x32), BK=16, reg-prefetch double buffer.
// ---------------------------------------------------------------------------
__device__ __forceinline__ void gemm64_body(
    const float* __restrict__ A, const float* __restrict__ W,
    const float* __restrict__ bias, float* __restrict__ C,
    int N, int K, int m0, int n0)
{
    constexpr int AS = 20;   // As[m][k], 16+4
    constexpr int BS = 72;   // Bs[k][n], 64+8
    __shared__ unsigned As[64 * AS];
    __shared__ unsigned Bs[16 * BS];

    const int tid  = threadIdx.x;
    const int warp = tid >> 5;
    const int lane = tid & 31;
    const int gid  = lane >> 2;
    const int tig  = lane & 3;
    const int wm   = (warp & 1) * 32;
    const int wn   = (warp >> 1) * 32;

    float4 ra[2], rb[2];
#pragma unroll
    for (int p = 0; p < 2; p++) {
        const int ia = tid + p * 128;
        ra[p] = *(const float4*)&A[(size_t)(m0 + (ia >> 2)) * K + (ia & 3) * 4];
        const int ib = tid + p * 128;
        rb[p] = *(const float4*)&W[(size_t)(ib >> 4) * N + n0 + (ib & 15) * 4];
    }

    float acc[2][4][4] = {};

    for (int k0 = 0; k0 < K; k0 += 16) {
#pragma unroll
        for (int p = 0; p < 2; p++) {
            const int ia = tid + p * 128;
            unsigned* pa = &As[(ia >> 2) * AS + (ia & 3) * 4];
            pa[0] = f2tf(ra[p].x); pa[1] = f2tf(ra[p].y);
            pa[2] = f2tf(ra[p].z); pa[3] = f2tf(ra[p].w);
            const int ib = tid + p * 128;
            unsigned* pb = &Bs[(ib >> 4) * BS + (ib & 15) * 4];
            pb[0] = f2tf(rb[p].x); pb[1] = f2tf(rb[p].y);
            pb[2] = f2tf(rb[p].z); pb[3] = f2tf(rb[p].w);
        }
        __syncthreads();
        if (k0 + 16 < K) {
#pragma unroll
            for (int p = 0; p < 2; p++) {
                const int ia = tid + p * 128;
                ra[p] = *(const float4*)&A[(size_t)(m0 + (ia >> 2)) * K + k0 + 16 + (ia & 3) * 4];
                const int ib = tid + p * 128;
                rb[p] = *(const float4*)&W[(size_t)(k0 + 16 + (ib >> 4)) * N + n0 + (ib & 15) * 4];
            }
        }
#pragma unroll
        for (int ks = 0; ks < 2; ks++) {
            unsigned afr[2][4];
#pragma unroll
            for (int mi = 0; mi < 2; mi++) {
                const int mr = wm + mi * 16 + gid;
                afr[mi][0] = As[mr * AS + ks * 8 + tig];
                afr[mi][1] = As[(mr + 8) * AS + ks * 8 + tig];
                afr[mi][2] = As[mr * AS + ks * 8 + tig + 4];
                afr[mi][3] = As[(mr + 8) * AS + ks * 8 + tig + 4];
            }
            unsigned bfr[4][2];
#pragma unroll
            for (int ni = 0; ni < 4; ni++) {
                const int nc = wn + ni * 8 + gid;
                bfr[ni][0] = Bs[(ks * 8 + tig) * BS + nc];
                bfr[ni][1] = Bs[(ks * 8 + tig + 4) * BS + nc];
            }
#pragma unroll
            for (int mi = 0; mi < 2; mi++)
#pragma unroll
                for (int ni = 0; ni < 4; ni++)
                    mma_tf32(acc[mi][ni], afr[mi][0], afr[mi][1], afr[mi][2], afr[mi][3],
                             bfr[ni][0], bfr[ni][1]);
        }
        __syncthreads();
    }

#pragma unroll
    for (int mi = 0; mi < 2; mi++) {
        const int row = m0 + wm + mi * 16 + gid;
#pragma unroll
        for (int ni = 0; ni < 4; ni++) {
            const int col = n0 + wn + ni * 8 + 2 * tig;
            const float2 bb = *(const float2*)&bias[col];
            float2 o0, o1;
            o0.x = acc[mi][ni][0] + bb.x; o0.y = acc[mi][ni][1] + bb.y;
            o1.x = acc[mi][ni][2] + bb.x; o1.y = acc[mi][ni][3] + bb.y;
            *(float2*)&C[(size_t)row * N + col]       = o0;
            *(float2*)&C[(size_t)(row + 8) * N + col] = o1;
        }
    }
}

// q/k/v projections batched over blockIdx.z
__global__ __launch_bounds__(128) void qkv_proj_kernel(
    const float* __restrict__ q, const float* __restrict__ k, const float* __restrict__ v,
    const float* __restrict__ Wq, const float* __restrict__ bq,
    const float* __restrict__ Wk, const float* __restrict__ bk,
    const float* __restrict__ Wv, const float* __restrict__ bv,
    float* __restrict__ qp, float* __restrict__ kp, float* __restrict__ vp)
{
    const int z = blockIdx.z;
    const float* A    = (z == 0) ? q  : (z == 1) ? k  : v;
    const float* W    = (z == 0) ? Wq : (z == 1) ? Wk : Wv;
    const float* bias = (z == 0) ? bq : (z == 1) ? bk : bv;
    float*       C    = (z == 0) ? qp : (z == 1) ? kp : vp;
    gemm64_body(A, W, bias, C, DA, DM, blockIdx.y * 64, blockIdx.x * 64);
}

// generic single GEMM (x projection, output projection)
__global__ __launch_bounds__(128) void gemm64_kernel(
    const float* __restrict__ A, const float* __restrict__ W,
    const float* __restrict__ bias, float* __restrict__ C, int N, int K)
{
    gemm64_body(A, W, bias, C, N, K, blockIdx.y * 64, blockIdx.x * 64);
}

// ---------------------------------------------------------------------------
// xdiff bias: logits[b,h,q,k] = 0.5 * sum_f xdiff[b,q,k,f] * x[b,q,h*F+f]
// One CTA per (b,q); reads xdiff exactly once, writes the logits buffer once.
// ---------------------------------------------------------------------------
__global__ __launch_bounds__(256) void xbias_kernel(
    const float* __restrict__ xdiff, const float* __restrict__ xg,
    float* __restrict__ logits)
{
    __shared__ float xh[H * F];
    const int bq  = blockIdx.x;
    const int b   = bq >> 10;
    const int qi  = bq & 1023;
    const int tid = threadIdx.x;
    if (tid < H * F) xh[tid] = xg[(size_t)bq * (H * F) + tid];
    __syncthreads();
    const float* xd = xdiff + (size_t)bq * S * F;
#pragma unroll
    for (int kt = 0; kt < 4; kt++) {
        const int k = kt * 256 + tid;
        const float4* src = (const float4*)&xd[(size_t)k * F];
        const float4 t0 = src[0], t1 = src[1], t2 = src[2], t3 = src[3];
        const float xv[16] = {t0.x, t0.y, t0.z, t0.w, t1.x, t1.y, t1.z, t1.w,
                              t2.x, t2.y, t2.z, t2.w, t3.x, t3.y, t3.z, t3.w};
#pragma unroll
        for (int h = 0; h < H; h++) {
            float s = 0.0f;
#pragma unroll
            for (int f = 0; f < F; f++) s = fmaf(xv[f], xh[h * F + f], s);
            logits[((size_t)(b * H + h) * S + qi) * S + k] = 0.5f * s;
        }
    }
}

// ---------------------------------------------------------------------------
// Fused attention, 512 threads / 16 warps, double-buffered K/V chunks.
//   L[32][1024] (smem) = bias tile (from gmem) + QK^T (tf32 mma, Q pre-scaled)
//   softmax(L) in smem -> write attn out
//   ctx tile = L @ V (tf32 mma) -> write ctx
// smem: L 32x1044 + Qs 32x68 + 2 x (128x72 KV buffers)  = 216,064 B
// ---------------------------------------------------------------------------
namespace {
constexpr int LSTR = 1044;
constexpr int QSTR = 68;
constexpr int KSTK = 68;   // K-phase layout stride inside buffer
constexpr int KSTV = 72;   // V-phase layout stride
constexpr int BUFW = 128 * KSTV;   // buffer size (words); holds either layout
constexpr int FATTN_SMEM = (32 * LSTR + 32 * QSTR + 2 * BUFW) * 4;
}

__global__ __launch_bounds__(512) void fattn_kernel(
    const float* __restrict__ qp, const float* __restrict__ kp,
    const float* __restrict__ vp, float* __restrict__ attn,
    float* __restrict__ ctx)
{
    extern __shared__ float smem[];
    float*    L  = smem;                               // 32 x LSTR
    unsigned* Qs = (unsigned*)(smem + 32 * LSTR);      // 32 x QSTR
    unsigned* KV = Qs + 32 * QSTR;                     // 2 x BUFW

    const int tid  = threadIdx.x;
    const int warp = tid >> 5;          // 0..15
    const int lane = tid & 31;
    const int gid  = lane >> 2;
    const int tig  = lane & 3;

    const int bh = blockIdx.y;           // b*H + h
    const int b  = bh >> 3;
    const int h  = bh & 7;
    const int q0 = blockIdx.x * 32;

    const size_t bh_row0 = ((size_t)bh * S + q0) * S;

    // load indices for K/V chunk staging: 4 float4 per thread (128 rows x 16 f)
    const int ldr = tid >> 4;            // not used directly; pattern via i below

    // ---- phase A: bias tile -> L ; Q tile -> Qs (prescaled, tf32) ----
#pragma unroll
    for (int p = 0; p < 16; p++) {
        const int i   = tid + p * 512;
        const int row = i >> 8;
        const int c4  = (i & 255) * 4;
        *(float4*)&L[row * LSTR + c4] = *(const float4*)&attn[bh_row0 + (size_t)row * S + c4];
    }
    {
        const int row = tid >> 4;
        const int c4  = (tid & 15) * 4;
        const float4 v = *(const float4*)&qp[(size_t)(b * S + q0 + row) * DA + h * 64 + c4];
        unsigned* p = &Qs[row * QSTR + c4];
        p[0] = f2tf(v.x * 0.125f); p[1] = f2tf(v.y * 0.125f);
        p[2] = f2tf(v.z * 0.125f); p[3] = f2tf(v.w * 0.125f);
    }

    const float* Kb = kp + (size_t)b * S * DA + h * 64;
    const float* Vb = vp + (size_t)b * S * DA + h * 64;

    // stage registers for double buffering
    float4 st[4];

    // ---- preload K chunk 0 ----
#pragma unroll
    for (int p = 0; p < 4; p++) {
        const int i = tid + p * 512;
        st[p] = *(const float4*)&Kb[(size_t)(i >> 4) * DA + (i & 15) * 4];
    }
#pragma unroll
    for (int p = 0; p < 4; p++) {
        const int i = tid + p * 512;
        uint4 u;
        u.x = f2tf(st[p].x); u.y = f2tf(st[p].y); u.z = f2tf(st[p].z); u.w = f2tf(st[p].w);
        *(uint4*)&KV[(i >> 4) * KSTK + (i & 15) * 4] = u;
    }
    __syncthreads();

    // ---- QK^T: accumulate into L; double-buffered chunks of 128 keys ----
    for (int kt = 0; kt < 8; kt++) {
        const unsigned* cur = KV + (kt & 1) * BUFW;
        if (kt < 7) {
            const int kbase = (kt + 1) * 128;
#pragma unroll
            for (int p = 0; p < 4; p++) {
                const int i = tid + p * 512;
                st[p] = *(const float4*)&Kb[(size_t)(kbase + (i >> 4)) * DA + (i & 15) * 4];
            }
        }

        float acc[2][4] = {};
#pragma unroll
        for (int ks = 0; ks < 8; ks++) {
            unsigned afr[2][4];
#pragma unroll
            for (int mi = 0; mi < 2; mi++) {
                const int mr = mi * 16 + gid;
                afr[mi][0] = Qs[mr * QSTR + ks * 8 + tig];
                afr[mi][1] = Qs[(mr + 8) * QSTR + ks * 8 + tig];
                afr[mi][2] = Qs[mr * QSTR + ks * 8 + tig + 4];
                afr[mi][3] = Qs[(mr + 8) * QSTR + ks * 8 + tig + 4];
            }
            const int nc = warp * 8 + gid;
            const unsigned b0 = cur[nc * KSTK + ks * 8 + tig];
            const unsigned b1 = cur[nc * KSTK + ks * 8 + tig + 4];
#pragma unroll
            for (int mi = 0; mi < 2; mi++)
                mma_tf32(acc[mi], afr[mi][0], afr[mi][1], afr[mi][2], afr[mi][3], b0, b1);
        }

        if (kt < 7) {
            unsigned* nxt = KV + ((kt + 1) & 1) * BUFW;
#pragma unroll
            for (int p = 0; p < 4; p++) {
                const int i = tid + p * 512;
                uint4 u;
                u.x = f2tf(st[p].x); u.y = f2tf(st[p].y);
                u.z = f2tf(st[p].z); u.w = f2tf(st[p].w);
                *(uint4*)&nxt[(i >> 4) * KSTK + (i & 15) * 4] = u;
            }
        }

        // epilogue: L += acc (warp owns cols warp*8..+8 of this chunk)
        const int col = kt * 128 + warp * 8 + tig * 2;
#pragma unroll
        for (int mi = 0; mi < 2; mi++) {
            const int row = mi * 16 + gid;
            L[row * LSTR + col]           += acc[mi][0];
            L[row * LSTR + col + 1]       += acc[mi][1];
            L[(row + 8) * LSTR + col]     += acc[mi][2];
            L[(row + 8) * LSTR + col + 1] += acc[mi][3];
        }
        __syncthreads();
    }

    // ---- preload V chunk 0 (overlaps with softmax) ----
#pragma unroll
    for (int p = 0; p < 4; p++) {
        const int i = tid + p * 512;
        st[p] = *(const float4*)&Vb[(size_t)(i >> 4) * DA + (i & 15) * 4];
    }

    // ---- softmax (warp per 2 rows), write attn out + normalized back to L ----
#pragma unroll
    for (int r = 0; r < 2; r++) {
        const int row = warp * 2 + r;
        float* Lr = &L[row * LSTR];
        float4 v[8];
        float m = -1e30f;
#pragma unroll
        for (int c = 0; c < 8; c++) {
            v[c] = *(float4*)&Lr[c * 128 + lane * 4];
            m = fmaxf(m, fmaxf(fmaxf(v[c].x, v[c].y), fmaxf(v[c].z, v[c].w)));
        }
#pragma unroll
        for (int o = 16; o; o >>= 1) m = fmaxf(m, __shfl_xor_sync(0xffffffffu, m, o));
        float s = 0.0f;
#pragma unroll
        for (int c = 0; c < 8; c++) {
            v[c].x = __expf(v[c].x - m); v[c].y = __expf(v[c].y - m);
            v[c].z = __expf(v[c].z - m); v[c].w = __expf(v[c].w - m);
            s += v[c].x + v[c].y + v[c].z + v[c].w;
        }
#pragma unroll
        for (int o = 16; o; o >>= 1) s += __shfl_xor_sync(0xffffffffu, s, o);
        const float inv = 1.0f / s;
        float* Ar = attn + bh_row0 + (size_t)row * S;
#pragma unroll
        for (int c = 0; c < 8; c++) {
            v[c].x *= inv; v[c].y *= inv; v[c].z *= inv; v[c].w *= inv;
            *(float4*)&Lr[c * 128 + lane * 4] = v[c];
            *(float4*)&Ar[c * 128 + lane * 4] = v[c];
        }
    }

    // store V chunk 0 into buf0 (L reads above are done; KV untouched by softmax)
    {
        unsigned* nxt = KV;
#pragma unroll
        for (int p = 0; p < 4; p++) {
            const int i = tid + p * 512;
            uint4 u;
            u.x = f2tf(st[p].x); u.y = f2tf(st[p].y);
            u.z = f2tf(st[p].z); u.w = f2tf(st[p].w);
            *(uint4*)&nxt[(i >> 4) * KSTV + (i & 15) * 4] = u;
        }
    }
    __syncthreads();

    // ---- PV: ctx tile [32,64] = L @ V; double-buffered chunks ----
    const int mi = warp & 1;
    const int wn = (warp >> 1) * 8;
    float pacc[4] = {};
    for (int kt = 0; kt < 8; kt++) {
        const unsigned* cur = KV + (kt & 1) * BUFW;
        if (kt < 7) {
            const int kbase = (kt + 1) * 128;
#pragma unroll
            for (int p = 0; p < 4; p++) {
                const int i = tid + p * 512;
                st[p] = *(const float4*)&Vb[(size_t)(kbase + (i >> 4)) * DA + (i & 15) * 4];
            }
        }

        const int k0 = kt * 128;
        const int row = mi * 16 + gid;
#pragma unroll
        for (int ks = 0; ks < 16; ks++) {
            const int kk = k0 + ks * 8;
            const unsigned a0 = f2tf(L[row * LSTR + kk + tig]);
            const unsigned a1 = f2tf(L[(row + 8) * LSTR + kk + tig]);
            const unsigned a2 = f2tf(L[row * LSTR + kk + tig + 4]);
            const unsigned a3 = f2tf(L[(row + 8) * LSTR + kk + tig + 4]);
            const unsigned b0 = cur[(ks * 8 + tig) * KSTV + wn + gid];
            const unsigned b1 = cur[(ks * 8 + tig + 4) * KSTV + wn + gid];
            mma_tf32(pacc, a0, a1, a2, a3, b0, b1);
        }

        if (kt < 7) {
            unsigned* nxt = KV + ((kt + 1) & 1) * BUFW;
#pragma unroll
            for (int p = 0; p < 4; p++) {
                const int i = tid + p * 512;
                uint4 u;
                u.x = f2tf(st[p].x); u.y = f2tf(st[p].y);
                u.z = f2tf(st[p].z); u.w = f2tf(st[p].w);
                *(uint4*)&nxt[(i >> 4) * KSTV + (i & 15) * 4] = u;
            }
        }
        __syncthreads();
    }
    {
        const int grow = b * S + q0 + mi * 16 + gid;
        const int col  = h * 64 + wn + tig * 2;
        float2 o0, o1;
        o0.x = pacc[0]; o0.y = pacc[1];
        o1.x = pacc[2]; o1.y = pacc[3];
        *(float2*)&ctx[(size_t)grow * DA + col]       = o0;
        *(float2*)&ctx[(size_t)(grow + 8) * DA + col] = o1;
    }
}

// ---------------------------------------------------------------------------
extern "C" void kernel_launch(void* const* d_in, const int* in_sizes, int n_in,
                              void* d_out, int out_size)
{
    const float* q     = (const float*)d_in[0];
    const float* k     = (const float*)d_in[1];
    const float* v     = (const float*)d_in[2];
    const float* xdiff = (const float*)d_in[3];
    const float* Wq    = (const float*)d_in[4];
    const float* bq    = (const float*)d_in[5];
    const float* Wk    = (const float*)d_in[6];
    const float* bk    = (const float*)d_in[7];
    const float* Wv    = (const float*)d_in[8];
    const float* bv    = (const float*)d_in[9];
    const float* Wx    = (const float*)d_in[10];
    const float* bx    = (const float*)d_in[11];
    const float* Wo    = (const float*)d_in[12];
    const float* bo    = (const float*)d_in[13];

    float* out_final = (float*)d_out;                       // [B,S,DM]
    float* attn      = out_final + (size_t)B * S * DM;      // [B,H,S,S]

    float *qp, *kp, *vp, *xg, *ctx;
    cudaGetSymbolAddress((void**)&qp,  g_qp);
    cudaGetSymbolAddress((void**)&kp,  g_kp);
    cudaGetSymbolAddress((void**)&vp,  g_vp);
    cudaGetSymbolAddress((void**)&xg,  g_x);
    cudaGetSymbolAddress((void**)&ctx, g_ctx);

    cudaFuncSetAttribute(fattn_kernel, cudaFuncAttributeMaxDynamicSharedMemorySize,
                         FATTN_SMEM);

    // 1. q/k/v projections, one batched launch: grid (N/64, M/64, 3)
    qkv_proj_kernel<<<dim3(DA / 64, (B * S) / 64, 3), 128>>>(
        q, k, v, Wq, bq, Wk, bk, Wv, bv, qp, kp, vp);

    // 2. x = qp @ Wx + bx : [4096,512] @ [512,128]
    gemm64_kernel<<<dim3((H * F) / 64, (B * S) / 64), 128>>>(qp, Wx, bx, xg, H * F, DA);

    // 3. xdiff relative bias -> writes entire logits buffer (attn region)
    xbias_kernel<<<B * S, 256>>>(xdiff, xg, attn);

    // 4. fused: logits += QK^T, softmax, attn out, PV -> ctx
    fattn_kernel<<<dim3(S / 32, B * H), 512, FATTN_SMEM>>>(qp, kp, vp, attn, ctx);

    // 5. output = ctx @ Wo + bo
    gemm64_kernel<<<dim3(DM / 64, (B * S) / 64), 128>>>(ctx, Wo, bo, out_final, DM, DA);
}

// round 9
// speedup vs baseline: 1.6877x; 1.0560x over previous
#include <cuda_runtime.h>

// Problem constants
namespace {
constexpr int B  = 4;
constexpr int S  = 1024;
constexpr int DM = 512;
constexpr int DA = 512;
constexpr int H  = 8;
constexpr int F  = 16;
}

// Scratch (static device globals -- no allocations allowed)
__device__ float g_qp [B * S * DA];      // 8 MB
__device__ float g_kp [B * S * DA];      // 8 MB
__device__ float g_vp [B * S * DA];      // 8 MB
__device__ float g_x  [B * S * H * F];   // 2 MB
__device__ float g_ctx[B * S * DA];      // 8 MB

// ---------------------------------------------------------------------------
// tf32 helpers
// ---------------------------------------------------------------------------
__device__ __forceinline__ unsigned f2tf(float f) {
    unsigned u;
    asm("cvt.rna.tf32.f32 %0, %1;" : "=r"(u) : "f"(f));
    return u;
}

__device__ __forceinline__ void mma_tf32(float c[4],
                                         unsigned a0, unsigned a1, unsigned a2, unsigned a3,
                                         unsigned b0, unsigned b1) {
    asm volatile(
        "mma.sync.aligned.m16n8k8.row.col.f32.tf32.tf32.f32 "
        "{%0,%1,%2,%3}, {%4,%5,%6,%7}, {%8,%9}, {%0,%1,%2,%3};"
        : "+f"(c[0]), "+f"(c[1]), "+f"(c[2]), "+f"(c[3])
        : "r"(a0), "r"(a1), "r"(a2), "r"(a3), "r"(b0), "r"(b1));
}

// ---------------------------------------------------------------------------
// 64x64-tile tf32 GEMM body: C[m0:64, n0:64] = A[M,K] @ W[K,N] + bias
// 128 threads (4 warps, warp-tile 32x32), BK=16, reg-prefetch double buffer.
// ---------------------------------------------------------------------------
__device__ __forceinline__ void gemm64_body(
    const float* __restrict__ A, const float* __restrict__ W,
    const float* __restrict__ bias, float* __restrict__ C,
    int N, int K, int m0, int n0)
{
    constexpr int AS = 20;   // As[m][k], 16+4
    constexpr int BS = 72;   // Bs[k][n], 64+8
    __shared__ unsigned As[64 * AS];
    __shared__ unsigned Bs[16 * BS];

    const int tid  = threadIdx.x;
    const int warp = tid >> 5;
    const int lane = tid & 31;
    const int gid  = lane >> 2;
    const int tig  = lane & 3;
    const int wm   = (warp & 1) * 32;
    const int wn   = (warp >> 1) * 32;

    float4 ra[2], rb[2];
#pragma unroll
    for (int p = 0; p < 2; p++) {
        const int ia = tid + p * 128;
        ra[p] = *(const float4*)&A[(size_t)(m0 + (ia >> 2)) * K + (ia & 3) * 4];
        const int ib = tid + p * 128;
        rb[p] = *(const float4*)&W[(size_t)(ib >> 4) * N + n0 + (ib & 15) * 4];
    }

    float acc[2][4][4] = {};

    for (int k0 = 0; k0 < K; k0 += 16) {
#pragma unroll
        for (int p = 0; p < 2; p++) {
            const int ia = tid + p * 128;
            unsigned* pa = &As[(ia >> 2) * AS + (ia & 3) * 4];
            pa[0] = f2tf(ra[p].x); pa[1] = f2tf(ra[p].y);
            pa[2] = f2tf(ra[p].z); pa[3] = f2tf(ra[p].w);
            const int ib = tid + p * 128;
            unsigned* pb = &Bs[(ib >> 4) * BS + (ib & 15) * 4];
            pb[0] = f2tf(rb[p].x); pb[1] = f2tf(rb[p].y);
            pb[2] = f2tf(rb[p].z); pb[3] = f2tf(rb[p].w);
        }
        __syncthreads();
        if (k0 + 16 < K) {
#pragma unroll
            for (int p = 0; p < 2; p++) {
                const int ia = tid + p * 128;
                ra[p] = *(const float4*)&A[(size_t)(m0 + (ia >> 2)) * K + k0 + 16 + (ia & 3) * 4];
                const int ib = tid + p * 128;
                rb[p] = *(const float4*)&W[(size_t)(k0 + 16 + (ib >> 4)) * N + n0 + (ib & 15) * 4];
            }
        }
#pragma unroll
        for (int ks = 0; ks < 2; ks++) {
            unsigned afr[2][4];
#pragma unroll
            for (int mi = 0; mi < 2; mi++) {
                const int mr = wm + mi * 16 + gid;
                afr[mi][0] = As[mr * AS + ks * 8 + tig];
                afr[mi][1] = As[(mr + 8) * AS + ks * 8 + tig];
                afr[mi][2] = As[mr * AS + ks * 8 + tig + 4];
                afr[mi][3] = As[(mr + 8) * AS + ks * 8 + tig + 4];
            }
            unsigned bfr[4][2];
#pragma unroll
            for (int ni = 0; ni < 4; ni++) {
                const int nc = wn + ni * 8 + gid;
                bfr[ni][0] = Bs[(ks * 8 + tig) * BS + nc];
                bfr[ni][1] = Bs[(ks * 8 + tig + 4) * BS + nc];
            }
#pragma unroll
            for (int mi = 0; mi < 2; mi++)
#pragma unroll
                for (int ni = 0; ni < 4; ni++)
                    mma_tf32(acc[mi][ni], afr[mi][0], afr[mi][1], afr[mi][2], afr[mi][3],
                             bfr[ni][0], bfr[ni][1]);
        }
        __syncthreads();
    }

#pragma unroll
    for (int mi = 0; mi < 2; mi++) {
        const int row = m0 + wm + mi * 16 + gid;
#pragma unroll
        for (int ni = 0; ni < 4; ni++) {
            const int col = n0 + wn + ni * 8 + 2 * tig;
            const float2 bb = *(const float2*)&bias[col];
            float2 o0, o1;
            o0.x = acc[mi][ni][0] + bb.x; o0.y = acc[mi][ni][1] + bb.y;
            o1.x = acc[mi][ni][2] + bb.x; o1.y = acc[mi][ni][3] + bb.y;
            *(float2*)&C[(size_t)row * N + col]       = o0;
            *(float2*)&C[(size_t)(row + 8) * N + col] = o1;
        }
    }
}

// q/k/v projections batched over blockIdx.z
__global__ __launch_bounds__(128) void qkv_proj_kernel(
    const float* __restrict__ q, const float* __restrict__ k, const float* __restrict__ v,
    const float* __restrict__ Wq, const float* __restrict__ bq,
    const float* __restrict__ Wk, const float* __restrict__ bk,
    const float* __restrict__ Wv, const float* __restrict__ bv,
    float* __restrict__ qp, float* __restrict__ kp, float* __restrict__ vp)
{
    const int z = blockIdx.z;
    const float* A    = (z == 0) ? q  : (z == 1) ? k  : v;
    const float* W    = (z == 0) ? Wq : (z == 1) ? Wk : Wv;
    const float* bias = (z == 0) ? bq : (z == 1) ? bk : bv;
    float*       C    = (z == 0) ? qp : (z == 1) ? kp : vp;
    gemm64_body(A, W, bias, C, DA, DM, blockIdx.y * 64, blockIdx.x * 64);
}

// generic single GEMM (x projection, output projection)
__global__ __launch_bounds__(128) void gemm64_kernel(
    const float* __restrict__ A, const float* __restrict__ W,
    const float* __restrict__ bias, float* __restrict__ C, int N, int K)
{
    gemm64_body(A, W, bias, C, N, K, blockIdx.y * 64, blockIdx.x * 64);
}

// ---------------------------------------------------------------------------
// xdiff bias: logits[b,h,q,k] = 0.5 * sum_f xdiff[b,q,k,f] * x[b,q,h*F+f]
// ---------------------------------------------------------------------------
__global__ __launch_bounds__(256) void xbias_kernel(
    const float* __restrict__ xdiff, const float* __restrict__ xg,
    float* __restrict__ logits)
{
    __shared__ float xh[H * F];
    const int bq  = blockIdx.x;
    const int b   = bq >> 10;
    const int qi  = bq & 1023;
    const int tid = threadIdx.x;
    if (tid < H * F) xh[tid] = xg[(size_t)bq * (H * F) + tid];
    __syncthreads();
    const float* xd = xdiff + (size_t)bq * S * F;
#pragma unroll
    for (int kt = 0; kt < 4; kt++) {
        const int k = kt * 256 + tid;
        const float4* src = (const float4*)&xd[(size_t)k * F];
        const float4 t0 = src[0], t1 = src[1], t2 = src[2], t3 = src[3];
        const float xv[16] = {t0.x, t0.y, t0.z, t0.w, t1.x, t1.y, t1.z, t1.w,
                              t2.x, t2.y, t2.z, t2.w, t3.x, t3.y, t3.z, t3.w};
#pragma unroll
        for (int h = 0; h < H; h++) {
            float s = 0.0f;
#pragma unroll
            for (int f = 0; f < F; f++) s = fmaf(xv[f], xh[h * F + f], s);
            logits[((size_t)(b * H + h) * S + qi) * S + k] = 0.5f * s;
        }
    }
}

// ---------------------------------------------------------------------------
// Fused attention, 512 threads / 16 warps, double-buffered K/V chunks.
//   acc = bias (LDG from gmem) + QK^T (Q frags hoisted to regs) -> STS to L
//   softmax(L float) -> attn gmem (float) + L (tf32 bits)
//   ctx tile = L @ V : ks-split across 2 warp groups, smem partial reduce
// smem: L 32x1044 + Qs/P 32x68 + 2 x (128x72 KV buffers) = 216,064 B
// ---------------------------------------------------------------------------
namespace {
constexpr int LSTR = 1044;
constexpr int QSTR = 68;
constexpr int KSTK = 68;   // K-phase layout stride inside buffer
constexpr int KSTV = 72;   // V-phase layout stride
constexpr int BUFW = 128 * KSTV;
constexpr int FATTN_SMEM = (32 * LSTR + 32 * QSTR + 2 * BUFW) * 4;
}

__global__ __launch_bounds__(512) void fattn_kernel(
    const float* __restrict__ qp, const float* __restrict__ kp,
    const float* __restrict__ vp, float* __restrict__ attn,
    float* __restrict__ ctx)
{
    extern __shared__ float smem[];
    float*    L  = smem;                               // 32 x LSTR (float / tf32 bits)
    unsigned* Lu = (unsigned*)smem;
    unsigned* Qs = (unsigned*)(smem + 32 * LSTR);      // 32 x QSTR (Q; later P partials)
    float*    P  = (float*)Qs;
    unsigned* KV = Qs + 32 * QSTR;                     // 2 x BUFW

    const int tid  = threadIdx.x;
    const int warp = tid >> 5;          // 0..15
    const int lane = tid & 31;
    const int gid  = lane >> 2;
    const int tig  = lane & 3;

    const int bh = blockIdx.y;           // b*H + h
    const int b  = bh >> 3;
    const int h  = bh & 7;
    const int q0 = blockIdx.x * 32;

    const size_t bh_row0 = ((size_t)bh * S + q0) * S;

    // ---- Q tile -> Qs (prescaled, tf32) ----
    {
        const int row = tid >> 4;
        const int c4  = (tid & 15) * 4;
        const float4 v = *(const float4*)&qp[(size_t)(b * S + q0 + row) * DA + h * 64 + c4];
        unsigned* p = &Qs[row * QSTR + c4];
        p[0] = f2tf(v.x * 0.125f); p[1] = f2tf(v.y * 0.125f);
        p[2] = f2tf(v.z * 0.125f); p[3] = f2tf(v.w * 0.125f);
    }
    __syncthreads();

    // ---- hoist Q fragments into registers (same for every chunk) ----
    unsigned qa[2][8][4];
#pragma unroll
    for (int mi = 0; mi < 2; mi++) {
        const int mr = mi * 16 + gid;
#pragma unroll
        for (int ks = 0; ks < 8; ks++) {
            qa[mi][ks][0] = Qs[mr * QSTR + ks * 8 + tig];
            qa[mi][ks][1] = Qs[(mr + 8) * QSTR + ks * 8 + tig];
            qa[mi][ks][2] = Qs[mr * QSTR + ks * 8 + tig + 4];
            qa[mi][ks][3] = Qs[(mr + 8) * QSTR + ks * 8 + tig + 4];
        }
    }

    const float* Kb = kp + (size_t)b * S * DA + h * 64;
    const float* Vb = vp + (size_t)b * S * DA + h * 64;

    float4 st[4];

    // ---- preload K chunk 0 ----
#pragma unroll
    for (int p = 0; p < 4; p++) {
        const int i = tid + p * 512;
        st[p] = *(const float4*)&Kb[(size_t)(i >> 4) * DA + (i & 15) * 4];
    }
#pragma unroll
    for (int p = 0; p < 4; p++) {
        const int i = tid + p * 512;
        uint4 u;
        u.x = f2tf(st[p].x); u.y = f2tf(st[p].y); u.z = f2tf(st[p].z); u.w = f2tf(st[p].w);
        *(uint4*)&KV[(i >> 4) * KSTK + (i & 15) * 4] = u;
    }
    __syncthreads();

    // ---- QK^T: acc initialized from gmem bias; result stored once to L ----
    for (int kt = 0; kt < 8; kt++) {
        const unsigned* cur = KV + (kt & 1) * BUFW;
        if (kt < 7) {
            const int kbase = (kt + 1) * 128;
#pragma unroll
            for (int p = 0; p < 4; p++) {
                const int i = tid + p * 512;
                st[p] = *(const float4*)&Kb[(size_t)(kbase + (i >> 4)) * DA + (i & 15) * 4];
            }
        }

        const int colb = kt * 128 + warp * 8 + tig * 2;
        float acc[2][4];
#pragma unroll
        for (int mi = 0; mi < 2; mi++) {
            const int row = mi * 16 + gid;
            const float2 t0 = *(const float2*)&attn[bh_row0 + (size_t)row * S + colb];
            const float2 t1 = *(const float2*)&attn[bh_row0 + (size_t)(row + 8) * S + colb];
            acc[mi][0] = t0.x; acc[mi][1] = t0.y; acc[mi][2] = t1.x; acc[mi][3] = t1.y;
        }

#pragma unroll
        for (int ks = 0; ks < 8; ks++) {
            const int nc = warp * 8 + gid;
            const unsigned b0 = cur[nc * KSTK + ks * 8 + tig];
            const unsigned b1 = cur[nc * KSTK + ks * 8 + tig + 4];
            mma_tf32(acc[0], qa[0][ks][0], qa[0][ks][1], qa[0][ks][2], qa[0][ks][3], b0, b1);
            mma_tf32(acc[1], qa[1][ks][0], qa[1][ks][1], qa[1][ks][2], qa[1][ks][3], b0, b1);
        }

        if (kt < 7) {
            unsigned* nxt = KV + ((kt + 1) & 1) * BUFW;
#pragma unroll
            for (int p = 0; p < 4; p++) {
                const int i = tid + p * 512;
                uint4 u;
                u.x = f2tf(st[p].x); u.y = f2tf(st[p].y);
                u.z = f2tf(st[p].z); u.w = f2tf(st[p].w);
                *(uint4*)&nxt[(i >> 4) * KSTK + (i & 15) * 4] = u;
            }
        }

        // store logits tile (single write, no RMW)
#pragma unroll
        for (int mi = 0; mi < 2; mi++) {
            const int row = mi * 16 + gid;
            float2 o0, o1;
            o0.x = acc[mi][0]; o0.y = acc[mi][1];
            o1.x = acc[mi][2]; o1.y = acc[mi][3];
            *(float2*)&L[row * LSTR + colb]       = o0;
            *(float2*)&L[(row + 8) * LSTR + colb] = o1;
        }
        __syncthreads();
    }

    // ---- preload V chunk 0 (overlaps with softmax) ----
#pragma unroll
    for (int p = 0; p < 4; p++) {
        const int i = tid + p * 512;
        st[p] = *(const float4*)&Vb[(size_t)(i >> 4) * DA + (i & 15) * 4];
    }

    // ---- softmax (warp per 2 rows): attn gmem (float) + L (tf32 bits) ----
#pragma unroll
    for (int r = 0; r < 2; r++) {
        const int row = warp * 2 + r;
        float* Lr = &L[row * LSTR];
        float4 v[8];
        float m = -1e30f;
#pragma unroll
        for (int c = 0; c < 8; c++) {
            v[c] = *(float4*)&Lr[c * 128 + lane * 4];
            m = fmaxf(m, fmaxf(fmaxf(v[c].x, v[c].y), fmaxf(v[c].z, v[c].w)));
        }
#pragma unroll
        for (int o = 16; o; o >>= 1) m = fmaxf(m, __shfl_xor_sync(0xffffffffu, m, o));
        float s = 0.0f;
#pragma unroll
        for (int c = 0; c < 8; c++) {
            v[c].x = __expf(v[c].x - m); v[c].y = __expf(v[c].y - m);
            v[c].z = __expf(v[c].z - m); v[c].w = __expf(v[c].w - m);
            s += v[c].x + v[c].y + v[c].z + v[c].w;
        }
#pragma unroll
        for (int o = 16; o; o >>= 1) s += __shfl_xor_sync(0xffffffffu, s, o);
        const float inv = 1.0f / s;
        float* Ar = attn + bh_row0 + (size_t)row * S;
#pragma unroll
        for (int c = 0; c < 8; c++) {
            v[c].x *= inv; v[c].y *= inv; v[c].z *= inv; v[c].w *= inv;
            *(float4*)&Ar[c * 128 + lane * 4] = v[c];
            uint4 u;
            u.x = f2tf(v[c].x); u.y = f2tf(v[c].y);
            u.z = f2tf(v[c].z); u.w = f2tf(v[c].w);
            *(uint4*)&Lu[row * LSTR + c * 128 + lane * 4] = u;
        }
    }

    // store V chunk 0 into buf0
    {
#pragma unroll
        for (int p = 0; p < 4; p++) {
            const int i = tid + p * 512;
            uint4 u;
            u.x = f2tf(st[p].x); u.y = f2tf(st[p].y);
            u.z = f2tf(st[p].z); u.w = f2tf(st[p].w);
            *(uint4*)&KV[(i >> 4) * KSTV + (i & 15) * 4] = u;
        }
    }
    __syncthreads();

    // ---- PV: ctx tile [32,64] = L @ V; ks split across 2 warp groups ----
    const int wg  = warp >> 3;          // 0/1: which half of each chunk's keys
    const int sub = warp & 7;
    const int mi  = sub & 1;
    const int wn  = (sub >> 1) * 16;    // 16 cols per warp (2 mma per A-frag)
    const int row = mi * 16 + gid;
    float pacc[2][4] = {};
    for (int kt = 0; kt < 8; kt++) {
        const unsigned* cur = KV + (kt & 1) * BUFW;
        if (kt < 7) {
            const int kbase = (kt + 1) * 128;
#pragma unroll
            for (int p = 0; p < 4; p++) {
                const int i = tid + p * 512;
                st[p] = *(const float4*)&Vb[(size_t)(kbase + (i >> 4)) * DA + (i & 15) * 4];
            }
        }

#pragma unroll
        for (int ks = 0; ks < 8; ks++) {
            const int ksc = wg * 8 + ks;
            const int kk  = kt * 128 + ksc * 8;
            const unsigned a0 = Lu[row * LSTR + kk + tig];
            const unsigned a1 = Lu[(row + 8) * LSTR + kk + tig];
            const unsigned a2 = Lu[row * LSTR + kk + tig + 4];
            const unsigned a3 = Lu[(row + 8) * LSTR + kk + tig + 4];
#pragma unroll
            for (int ni = 0; ni < 2; ni++) {
                const unsigned b0 = cur[(ksc * 8 + tig) * KSTV + wn + ni * 8 + gid];
                const unsigned b1 = cur[(ksc * 8 + tig + 4) * KSTV + wn + ni * 8 + gid];
                mma_tf32(pacc[ni], a0, a1, a2, a3, b0, b1);
            }
        }

        if (kt < 7) {
            unsigned* nxt = KV + ((kt + 1) & 1) * BUFW;
#pragma unroll
            for (int p = 0; p < 4; p++) {
                const int i = tid + p * 512;
                uint4 u;
                u.x = f2tf(st[p].x); u.y = f2tf(st[p].y);
                u.z = f2tf(st[p].z); u.w = f2tf(st[p].w);
                *(uint4*)&nxt[(i >> 4) * KSTV + (i & 15) * 4] = u;
            }
        }
        __syncthreads();
    }

    // reduce the two ks-half partials and store ctx
    if (wg == 1) {
#pragma unroll
        for (int ni = 0; ni < 2; ni++) {
            const int col = wn + ni * 8 + tig * 2;
            float2 o0, o1;
            o0.x = pacc[ni][0]; o0.y = pacc[ni][1];
            o1.x = pacc[ni][2]; o1.y = pacc[ni][3];
            *(float2*)&P[row * QSTR + col]       = o0;
            *(float2*)&P[(row + 8) * QSTR + col] = o1;
        }
    }
    __syncthreads();
    if (wg == 0) {
        const int grow = b * S + q0 + row;
#pragma unroll
        for (int ni = 0; ni < 2; ni++) {
            const int col = wn + ni * 8 + tig * 2;
            const float2 p0 = *(const float2*)&P[row * QSTR + col];
            const float2 p1 = *(const float2*)&P[(row + 8) * QSTR + col];
            float2 o0, o1;
            o0.x = pacc[ni][0] + p0.x; o0.y = pacc[ni][1] + p0.y;
            o1.x = pacc[ni][2] + p1.x; o1.y = pacc[ni][3] + p1.y;
            *(float2*)&ctx[(size_t)grow * DA + h * 64 + col]       = o0;
            *(float2*)&ctx[(size_t)(grow + 8) * DA + h * 64 + col] = o1;
        }
    }
}

// ---------------------------------------------------------------------------
extern "C" void kernel_launch(void* const* d_in, const int* in_sizes, int n_in,
                              void* d_out, int out_size)
{
    const float* q     = (const float*)d_in[0];
    const float* k     = (const float*)d_in[1];
    const float* v     = (const float*)d_in[2];
    const float* xdiff = (const float*)d_in[3];
    const float* Wq    = (const float*)d_in[4];
    const float* bq    = (const float*)d_in[5];
    const float* Wk    = (const float*)d_in[6];
    const float* bk    = (const float*)d_in[7];
    const float* Wv    = (const float*)d_in[8];
    const float* bv    = (const float*)d_in[9];
    const float* Wx    = (const float*)d_in[10];
    const float* bx    = (const float*)d_in[11];
    const float* Wo    = (const float*)d_in[12];
    const float* bo    = (const float*)d_in[13];

    float* out_final = (float*)d_out;                       // [B,S,DM]
    float* attn      = out_final + (size_t)B * S * DM;      // [B,H,S,S]

    float *qp, *kp, *vp, *xg, *ctx;
    cudaGetSymbolAddress((void**)&qp,  g_qp);
    cudaGetSymbolAddress((void**)&kp,  g_kp);
    cudaGetSymbolAddress((void**)&vp,  g_vp);
    cudaGetSymbolAddress((void**)&xg,  g_x);
    cudaGetSymbolAddress((void**)&ctx, g_ctx);

    cudaFuncSetAttribute(fattn_kernel, cudaFuncAttributeMaxDynamicSharedMemorySize,
                         FATTN_SMEM);

    // 1. q/k/v projections, one batched launch
    qkv_proj_kernel<<<dim3(DA / 64, (B * S) / 64, 3), 128>>>(
        q, k, v, Wq, bq, Wk, bk, Wv, bv, qp, kp, vp);

    // 2. x = qp @ Wx + bx
    gemm64_kernel<<<dim3((H * F) / 64, (B * S) / 64), 128>>>(qp, Wx, bx, xg, H * F, DA);

    // 3. xdiff relative bias -> logits buffer (attn region)
    xbias_kernel<<<B * S, 256>>>(xdiff, xg, attn);

    // 4. fused: logits = bias + QK^T, softmax, attn out, PV -> ctx
    fattn_kernel<<<dim3(S / 32, B * H), 512, FATTN_SMEM>>>(qp, kp, vp, attn, ctx);

    // 5. output = ctx @ Wo + bo
    gemm64_kernel<<<dim3(DM / 64, (B * S) / 64), 128>>>(ctx, Wo, bo, out_final, DM, DA);
}